// round 3
// baseline (speedup 1.0000x reference)
#include <cuda_runtime.h>
#include <cstdint>

// ============================================================================
// PointPairwiseRelation3 — legacy mma.sync tf32 (sm_80+ PTX, safe on compute_103)
//
// Math:
//   pre[b,n,j,k,o] = base[b,n,o] + U1[b,j,o] + U2[b,k,o]
//     base = x@(Wa-Wb-Wc) + b1,  U1 = x1@Wb,  U2 = x2@Wc
//   h = relu(pre);  u = relu(h @ W2 + b2)
//   out[b,n,p] = max_{j,k} u[...,p]   (p < 8)
//              = mean_{j,k} u[...,p]  (p >= 8)
//
// main_kernel: 512 CTAs (one per (b,n)), 128 threads (4 warps).
// Warp w owns j in [w*32, w*32+32); per j, 8 k-tiles of 16 rows.
// Per tile: A[16,16] generated in registers (relu'd, tf32-rounded),
// 4x mma.sync.m16n8k8.tf32 with D preloaded with bias, 12-op epilogue.
// ============================================================================

__device__ float g_base[2 * 256 * 16];
__device__ float g_U1[2 * 128 * 16];
__device__ float g_U2[2 * 128 * 16];

__device__ __forceinline__ uint32_t cvt_tf32(float v) {
    uint32_t r;
    asm("cvt.rna.tf32.f32 %0, %1;" : "=r"(r) : "f"(v));
    return r;
}

__device__ __forceinline__ void mma_tf32(float d[4],
                                         uint32_t a0, uint32_t a1, uint32_t a2, uint32_t a3,
                                         uint32_t b0, uint32_t b1) {
    asm volatile(
        "mma.sync.aligned.m16n8k8.row.col.f32.tf32.tf32.f32 "
        "{%0,%1,%2,%3}, {%4,%5,%6,%7}, {%8,%9}, {%0,%1,%2,%3};\n"
        : "+f"(d[0]), "+f"(d[1]), "+f"(d[2]), "+f"(d[3])
        : "r"(a0), "r"(a1), "r"(a2), "r"(a3), "r"(b0), "r"(b1));
}

// ============================================================================
// Precompute kernel: base, U1, U2 (1024 rows x 16 outputs, K=16 dots)
// ============================================================================
__global__ void __launch_bounds__(256) pre_kernel(const float* __restrict__ x,
                                                  const float* __restrict__ x1,
                                                  const float* __restrict__ x2,
                                                  const float* __restrict__ W1,
                                                  const float* __restrict__ b1) {
    int t = blockIdx.x * 256 + threadIdx.x;
    if (t >= 16384) return;
    int o = t & 15;
    int row = t >> 4;
    if (row < 512) {
        const float* xr = x + row * 16;
        float s = b1[o];
        #pragma unroll
        for (int c = 0; c < 16; ++c)
            s += xr[c] * (W1[c * 16 + o] - W1[(16 + c) * 16 + o] - W1[(32 + c) * 16 + o]);
        g_base[row * 16 + o] = s;
    } else if (row < 768) {
        int r = row - 512;
        const float* xr = x1 + r * 16;
        float s = 0.f;
        #pragma unroll
        for (int c = 0; c < 16; ++c)
            s += xr[c] * W1[(16 + c) * 16 + o];
        g_U1[r * 16 + o] = s;
    } else {
        int r = row - 768;
        const float* xr = x2 + r * 16;
        float s = 0.f;
        #pragma unroll
        for (int c = 0; c < 16; ++c)
            s += xr[c] * W1[(32 + c) * 16 + o];
        g_U2[r * 16 + o] = s;
    }
}

// ============================================================================
// Main kernel
// ============================================================================
// Permuted SMEM layout: row r holds chunks c = 0..3, chunk c = float4 of
// cols {c, c+4, c+8, c+12}. Lane (t = lane&3) loads chunk t -> exactly the
// 4 o-columns its A-fragment registers need.
__global__ void __launch_bounds__(128)
main_kernel(const float* __restrict__ W2, const float* __restrict__ b2,
            float* __restrict__ out) {
    __shared__ float4 sWU2[128][4];   // base[bn] + U2[b,k]  (permuted)
    __shared__ float4 sU1[128][4];    // U1[b,j]             (permuted)
    __shared__ float  sRed[4][16];

    const int tid = threadIdx.x;
    const int wid = tid >> 5;
    const int lane = tid & 31;
    const int g = lane >> 2;          // groupID (row within tile / n for B)
    const int t4 = lane & 3;          // threadID-in-group (col chunk / k for B)
    const int bn = blockIdx.x;
    const int b = bn >> 8;

    // ---- SMEM init: thread t handles row k=j=t ----
    {
        const float* basep = g_base + bn * 16;
        const float* u2p = g_U2 + (b * 128 + tid) * 16;
        const float* u1p = g_U1 + (b * 128 + tid) * 16;
        float v[16], u[16];
        #pragma unroll
        for (int o = 0; o < 16; ++o) {
            v[o] = basep[o] + u2p[o];
            u[o] = u1p[o];
        }
        #pragma unroll
        for (int c = 0; c < 4; ++c) {
            sWU2[tid][c] = make_float4(v[c], v[c + 4], v[c + 8], v[c + 12]);
            sU1[tid][c]  = make_float4(u[c], u[c + 4], u[c + 8], u[c + 12]);
        }
    }

    // ---- B fragments (W2 rounded to tf32) + bias regs ----
    // B[k,n] for nt (n-tile), ks (k-step): b0 k=ks*8+t4, b1 k=ks*8+t4+4; n=nt*8+g
    uint32_t Bf[2][2][2];
    #pragma unroll
    for (int nt = 0; nt < 2; ++nt)
        #pragma unroll
        for (int ks = 0; ks < 2; ++ks) {
            Bf[nt][ks][0] = cvt_tf32(W2[(ks * 8 + t4) * 16 + nt * 8 + g]);
            Bf[nt][ks][1] = cvt_tf32(W2[(ks * 8 + t4 + 4) * 16 + nt * 8 + g]);
        }
    float bias[4];
    bias[0] = b2[2 * t4];
    bias[1] = b2[2 * t4 + 1];
    bias[2] = b2[8 + 2 * t4];
    bias[3] = b2[8 + 2 * t4 + 1];

    float accm0 = 0.f, accm1 = 0.f;   // max accum, cols 2*t4, 2*t4+1
    float accs0 = 0.f, accs1 = 0.f;   // sum accum, cols 8+2*t4, 8+2*t4+1

    __syncthreads();

    // ---- main loop: 32 j x 8 k-tiles per warp ----
    const int j0 = wid * 32;
    for (int jj = 0; jj < 32; ++jj) {
        const float4 u1v = sU1[j0 + jj][t4];
        #pragma unroll
        for (int kt = 0; kt < 8; ++kt) {
            const int r0 = kt * 16 + g;
            const float4 wa = sWU2[r0][t4];
            const float4 wb = sWU2[r0 + 8][t4];

            // A fragments: relu(pre), round-to-nearest tf32
            // k-step 0: cols {c, c+4}; k-step 1: cols {c+8, c+12}
            uint32_t a00 = cvt_tf32(fmaxf(wa.x + u1v.x, 0.f));  // row g,   col c
            uint32_t a01 = cvt_tf32(fmaxf(wb.x + u1v.x, 0.f));  // row g+8, col c
            uint32_t a02 = cvt_tf32(fmaxf(wa.y + u1v.y, 0.f));  // row g,   col c+4
            uint32_t a03 = cvt_tf32(fmaxf(wb.y + u1v.y, 0.f));  // row g+8, col c+4
            uint32_t a10 = cvt_tf32(fmaxf(wa.z + u1v.z, 0.f));
            uint32_t a11 = cvt_tf32(fmaxf(wb.z + u1v.z, 0.f));
            uint32_t a12 = cvt_tf32(fmaxf(wa.w + u1v.w, 0.f));
            uint32_t a13 = cvt_tf32(fmaxf(wb.w + u1v.w, 0.f));

            // D preloaded with bias (folds +b2 into the MMA)
            float d0[4] = {bias[0], bias[1], bias[0], bias[1]};
            float d1[4] = {bias[2], bias[3], bias[2], bias[3]};

            mma_tf32(d0, a00, a01, a02, a03, Bf[0][0][0], Bf[0][0][1]);
            mma_tf32(d0, a10, a11, a12, a13, Bf[0][1][0], Bf[0][1][1]);
            mma_tf32(d1, a00, a01, a02, a03, Bf[1][0][0], Bf[1][0][1]);
            mma_tf32(d1, a10, a11, a12, a13, Bf[1][1][0], Bf[1][1][1]);

            // epilogue: max half (relu folded into max: acc >= 0 always)
            accm0 = fmaxf(accm0, d0[0]);
            accm1 = fmaxf(accm1, d0[1]);
            accm0 = fmaxf(accm0, d0[2]);
            accm1 = fmaxf(accm1, d0[3]);
            // mean half: relu then sum
            accs0 += fmaxf(d1[0], 0.f);
            accs1 += fmaxf(d1[1], 0.f);
            accs0 += fmaxf(d1[2], 0.f);
            accs1 += fmaxf(d1[3], 0.f);
        }
    }

    // ---- intra-warp reduction over row-groups (lanes differing in g) ----
    #pragma unroll
    for (int s = 4; s <= 16; s <<= 1) {
        accm0 = fmaxf(accm0, __shfl_xor_sync(0xffffffffu, accm0, s));
        accm1 = fmaxf(accm1, __shfl_xor_sync(0xffffffffu, accm1, s));
        accs0 += __shfl_xor_sync(0xffffffffu, accs0, s);
        accs1 += __shfl_xor_sync(0xffffffffu, accs1, s);
    }
    if (lane < 4) {
        sRed[wid][2 * lane]     = accm0;
        sRed[wid][2 * lane + 1] = accm1;
        sRed[wid][8 + 2 * lane]     = accs0;
        sRed[wid][8 + 2 * lane + 1] = accs1;
    }
    __syncthreads();

    // ---- cross-warp combine + writeout ----
    if (tid < 16) {
        float v = sRed[0][tid];
        if (tid < 8) {
            #pragma unroll
            for (int w = 1; w < 4; ++w) v = fmaxf(v, sRed[w][tid]);
        } else {
            #pragma unroll
            for (int w = 1; w < 4; ++w) v += sRed[w][tid];
            v *= (1.0f / 16384.0f);
        }
        out[bn * 16 + tid] = v;
    }
}

// ============================================================================
// Launch
// ============================================================================
extern "C" void kernel_launch(void* const* d_in, const int* in_sizes, int n_in,
                              void* d_out, int out_size) {
    const float* x  = (const float*)d_in[0];
    const float* x1 = (const float*)d_in[1];
    const float* x2 = (const float*)d_in[2];
    const float* W1 = (const float*)d_in[3];
    const float* b1 = (const float*)d_in[4];
    const float* W2 = (const float*)d_in[5];
    const float* b2 = (const float*)d_in[6];
    float* out = (float*)d_out;

    pre_kernel<<<64, 256>>>(x, x1, x2, W1, b1);
    main_kernel<<<512, 128>>>(W2, b2, out);
}

// round 4
// speedup vs baseline: 1.4812x; 1.4812x over previous
#include <cuda_runtime.h>
#include <cstdint>

// ============================================================================
// PointPairwiseRelation3 — mma.sync tf32, j-split x2 for occupancy
//
//   pre[b,n,j,k,o] = base[b,n,o] + U1[b,j,o] + U2[b,k,o]
//     base = x@(Wa-Wb-Wc) + b1,  U1 = x1@Wb,  U2 = x2@Wc
//   h = relu(pre);  u = relu(h @ W2 + b2)
//   out[b,n,p] = max_{j,k} u   (p<8) ;  mean_{j,k} u  (p>=8)
//
// main_kernel: 1024 CTAs = (b,n) x jhalf, 128 threads (4 warps).
// Warp w of half hf owns j in [(hf*4+w)*16, +16); per j, 8 k-tiles of 16 rows.
// Per tile: A[16,16] in regs (relu, tf32-by-truncation), 4x mma.m16n8k8.tf32
// with bias as the C operand, 12-op epilogue. CTA partials combined with
// atomicMax (int bits, values >= 0) / atomicAdd.
// ============================================================================

__device__ float g_base[2 * 256 * 16];
__device__ float g_U1[2 * 128 * 16];
__device__ float g_U2[2 * 128 * 16];

__device__ __forceinline__ uint32_t cvt_tf32(float v) {
    uint32_t r;
    asm("cvt.rna.tf32.f32 %0, %1;" : "=r"(r) : "f"(v));
    return r;
}

// D = A*B + D   (accumulate)
__device__ __forceinline__ void mma_acc(float d[4],
                                        uint32_t a0, uint32_t a1, uint32_t a2, uint32_t a3,
                                        uint32_t b0, uint32_t b1) {
    asm("mma.sync.aligned.m16n8k8.row.col.f32.tf32.tf32.f32 "
        "{%0,%1,%2,%3}, {%4,%5,%6,%7}, {%8,%9}, {%0,%1,%2,%3};\n"
        : "+f"(d[0]), "+f"(d[1]), "+f"(d[2]), "+f"(d[3])
        : "r"(a0), "r"(a1), "r"(a2), "r"(a3), "r"(b0), "r"(b1));
}

// D = A*B + {c0,c1,c0,c1}   (bias as C operand — no per-tile MOV init)
__device__ __forceinline__ void mma_bias(float d[4],
                                         uint32_t a0, uint32_t a1, uint32_t a2, uint32_t a3,
                                         uint32_t b0, uint32_t b1, float c0, float c1) {
    asm("mma.sync.aligned.m16n8k8.row.col.f32.tf32.tf32.f32 "
        "{%0,%1,%2,%3}, {%4,%5,%6,%7}, {%8,%9}, {%10,%11,%10,%11};\n"
        : "=f"(d[0]), "=f"(d[1]), "=f"(d[2]), "=f"(d[3])
        : "r"(a0), "r"(a1), "r"(a2), "r"(a3), "r"(b0), "r"(b1), "f"(c0), "f"(c1));
}

// ============================================================================
// Precompute kernel: base, U1, U2 + zero-init d_out
// ============================================================================
__global__ void __launch_bounds__(256) pre_kernel(const float* __restrict__ x,
                                                  const float* __restrict__ x1,
                                                  const float* __restrict__ x2,
                                                  const float* __restrict__ W1,
                                                  const float* __restrict__ b1,
                                                  float* __restrict__ out) {
    int t = blockIdx.x * 256 + threadIdx.x;
    if (t < 8192) out[t] = 0.f;   // 512 x 16 outputs, accumulated by atomics
    if (t >= 16384) return;
    int o = t & 15;
    int row = t >> 4;
    if (row < 512) {
        const float* xr = x + row * 16;
        float s = b1[o];
        #pragma unroll
        for (int c = 0; c < 16; ++c)
            s += xr[c] * (W1[c * 16 + o] - W1[(16 + c) * 16 + o] - W1[(32 + c) * 16 + o]);
        g_base[row * 16 + o] = s;
    } else if (row < 768) {
        int r = row - 512;
        const float* xr = x1 + r * 16;
        float s = 0.f;
        #pragma unroll
        for (int c = 0; c < 16; ++c)
            s += xr[c] * W1[(16 + c) * 16 + o];
        g_U1[r * 16 + o] = s;
    } else {
        int r = row - 768;
        const float* xr = x2 + r * 16;
        float s = 0.f;
        #pragma unroll
        for (int c = 0; c < 16; ++c)
            s += xr[c] * W1[(32 + c) * 16 + o];
        g_U2[r * 16 + o] = s;
    }
}

// ============================================================================
// Main kernel
// ============================================================================
// Permuted SMEM: row r, chunk c = float4 of cols {c, c+4, c+8, c+12}.
// Lane's t4 = lane&3 selects exactly the 4 o-columns its A-fragments need.
__global__ void __launch_bounds__(128)
main_kernel(const float* __restrict__ W2, const float* __restrict__ b2,
            float* __restrict__ out) {
    __shared__ float4 sWU2[128][4];   // base[bn] + U2[b,k]  (permuted, all k)
    __shared__ float4 sU1[64][4];     // U1[b,j] for this CTA's j-half
    __shared__ float  sRed[4][16];

    const int tid = threadIdx.x;
    const int wid = tid >> 5;
    const int lane = tid & 31;
    const int g = lane >> 2;          // row-in-tile / n for B
    const int t4 = lane & 3;          // col chunk / k for B
    const int bn = blockIdx.x >> 1;
    const int hf = blockIdx.x & 1;    // j half
    const int b = bn >> 8;

    // ---- SMEM init ----
    {
        const float* basep = g_base + bn * 16;
        const float* u2p = g_U2 + (b * 128 + tid) * 16;
        float v[16];
        #pragma unroll
        for (int o = 0; o < 16; ++o) v[o] = basep[o] + u2p[o];
        #pragma unroll
        for (int c = 0; c < 4; ++c)
            sWU2[tid][c] = make_float4(v[c], v[c + 4], v[c + 8], v[c + 12]);
    }
    if (tid < 64) {
        const float* u1p = g_U1 + (b * 128 + hf * 64 + tid) * 16;
        float u[16];
        #pragma unroll
        for (int o = 0; o < 16; ++o) u[o] = u1p[o];
        #pragma unroll
        for (int c = 0; c < 4; ++c)
            sU1[tid][c] = make_float4(u[c], u[c + 4], u[c + 8], u[c + 12]);
    }

    // ---- B fragments (W2, RN tf32) + bias ----
    uint32_t Bf[2][2][2];
    #pragma unroll
    for (int nt = 0; nt < 2; ++nt)
        #pragma unroll
        for (int ks = 0; ks < 2; ++ks) {
            Bf[nt][ks][0] = cvt_tf32(W2[(ks * 8 + t4) * 16 + nt * 8 + g]);
            Bf[nt][ks][1] = cvt_tf32(W2[(ks * 8 + t4 + 4) * 16 + nt * 8 + g]);
        }
    float bias[4];
    bias[0] = b2[2 * t4];
    bias[1] = b2[2 * t4 + 1];
    bias[2] = b2[8 + 2 * t4];
    bias[3] = b2[8 + 2 * t4 + 1];

    float accm0 = 0.f, accm1 = 0.f;   // max accum (cols 2t4, 2t4+1)
    float accs0 = 0.f, accs1 = 0.f;   // sum accum (cols 8+2t4, 8+2t4+1)

    __syncthreads();

    // ---- main loop: 16 j x 8 k-tiles per warp ----
    const int j0 = wid * 16;
    for (int jj = 0; jj < 16; ++jj) {
        const float4 u1v = sU1[j0 + jj][t4];
        #pragma unroll
        for (int kt = 0; kt < 8; ++kt) {
            const int r0 = kt * 16 + g;
            const float4 wa = sWU2[r0][t4];
            const float4 wb = sWU2[r0 + 8][t4];

            // A fragments: relu(pre); tf32 by truncation (HMMA ignores low bits)
            uint32_t a00 = __float_as_uint(fmaxf(wa.x + u1v.x, 0.f));
            uint32_t a01 = __float_as_uint(fmaxf(wb.x + u1v.x, 0.f));
            uint32_t a02 = __float_as_uint(fmaxf(wa.y + u1v.y, 0.f));
            uint32_t a03 = __float_as_uint(fmaxf(wb.y + u1v.y, 0.f));
            uint32_t a10 = __float_as_uint(fmaxf(wa.z + u1v.z, 0.f));
            uint32_t a11 = __float_as_uint(fmaxf(wb.z + u1v.z, 0.f));
            uint32_t a12 = __float_as_uint(fmaxf(wa.w + u1v.w, 0.f));
            uint32_t a13 = __float_as_uint(fmaxf(wb.w + u1v.w, 0.f));

            float d0[4], d1[4];
            mma_bias(d0, a00, a01, a02, a03, Bf[0][0][0], Bf[0][0][1], bias[0], bias[1]);
            mma_acc (d0, a10, a11, a12, a13, Bf[0][1][0], Bf[0][1][1]);
            mma_bias(d1, a00, a01, a02, a03, Bf[1][0][0], Bf[1][0][1], bias[2], bias[3]);
            mma_acc (d1, a10, a11, a12, a13, Bf[1][1][0], Bf[1][1][1]);

            // max half: relu folded into max (acc starts at 0)
            accm0 = fmaxf(accm0, d0[0]);
            accm1 = fmaxf(accm1, d0[1]);
            accm0 = fmaxf(accm0, d0[2]);
            accm1 = fmaxf(accm1, d0[3]);
            // mean half: relu then sum
            accs0 += fmaxf(d1[0], 0.f);
            accs1 += fmaxf(d1[1], 0.f);
            accs0 += fmaxf(d1[2], 0.f);
            accs1 += fmaxf(d1[3], 0.f);
        }
    }

    // ---- intra-warp reduction over g lanes ----
    #pragma unroll
    for (int s = 4; s <= 16; s <<= 1) {
        accm0 = fmaxf(accm0, __shfl_xor_sync(0xffffffffu, accm0, s));
        accm1 = fmaxf(accm1, __shfl_xor_sync(0xffffffffu, accm1, s));
        accs0 += __shfl_xor_sync(0xffffffffu, accs0, s);
        accs1 += __shfl_xor_sync(0xffffffffu, accs1, s);
    }
    if (lane < 4) {
        sRed[wid][2 * lane]         = accm0;
        sRed[wid][2 * lane + 1]     = accm1;
        sRed[wid][8 + 2 * lane]     = accs0;
        sRed[wid][8 + 2 * lane + 1] = accs1;
    }
    __syncthreads();

    // ---- cross-warp combine + atomic merge of the two j-halves ----
    if (tid < 16) {
        float v = sRed[0][tid];
        if (tid < 8) {
            #pragma unroll
            for (int w = 1; w < 4; ++w) v = fmaxf(v, sRed[w][tid]);
            atomicMax((int*)(out + bn * 16 + tid), __float_as_int(v));  // v >= 0
        } else {
            #pragma unroll
            for (int w = 1; w < 4; ++w) v += sRed[w][tid];
            atomicAdd(out + bn * 16 + tid, v * (1.0f / 16384.0f));
        }
    }
}

// ============================================================================
// Launch
// ============================================================================
extern "C" void kernel_launch(void* const* d_in, const int* in_sizes, int n_in,
                              void* d_out, int out_size) {
    const float* x  = (const float*)d_in[0];
    const float* x1 = (const float*)d_in[1];
    const float* x2 = (const float*)d_in[2];
    const float* W1 = (const float*)d_in[3];
    const float* b1 = (const float*)d_in[4];
    const float* W2 = (const float*)d_in[5];
    const float* b2 = (const float*)d_in[6];
    float* out = (float*)d_out;

    pre_kernel<<<64, 256>>>(x, x1, x2, W1, b1, out);
    main_kernel<<<1024, 128>>>(W2, b2, out);
}

// round 6
// speedup vs baseline: 1.8191x; 1.2282x over previous
#include <cuda_runtime.h>
#include <cuda_fp16.h>
#include <cstdint>

// ============================================================================
// PointPairwiseRelation3 — fp16 mma.sync m16n8k16, pre-permuted f16 operands
//
//   pre[b,n,j,k,o] = base[b,n,o] + U1[b,j,o] + U2[b,k,o]
//     base = x@(Wa-Wb-Wc) + b1,  U1 = x1@Wb,  U2 = x2@Wc
//   h = relu(pre);  u = relu(h @ W2 + b2)
//   out[b,n,p] = max_{j,k} u   (p<8) ;  mean_{j,k} u  (p>=8)
//
// pre1: base/U1/U2 in f32 + zero d_out.
// pre2: w-image  g_wh[bn][kt][g][t4] = f16x2 fragment-layout of base[bn]+U2[k]
//       u1-image g_u1h[b][j][t4]     = f16x2 fragment-layout of U1
// main: 4096 CTAs = (b,n) x 8 j-octets, 128 thr. Warp: 4 j x 8 k-tiles.
//       Per tile: 1 LDS.128 + 4 HADD2 + 4 HMAX2(relu) + 2 HMMA(k16) + 12 epi.
//       Partials merged with atomicMax(bits)/atomicAdd.
// ============================================================================

__device__ float g_base[2 * 256 * 16];
__device__ float g_U1[2 * 128 * 16];
__device__ float g_U2[2 * 128 * 16];
__device__ uint4 g_wh[512 * 8 * 8 * 4];   // [bn][kt][g][t4] -> 2MB
__device__ uint2 g_u1h[2 * 128 * 4];      // [b][j][t4]

__device__ __forceinline__ uint32_t h2u(__half2 h) {
    return *reinterpret_cast<uint32_t*>(&h);
}
__device__ __forceinline__ uint32_t pack_h2(float lo, float hi) {
    __half2 h = __floats2half2_rn(lo, hi);
    return h2u(h);
}

// D = A*B + {c0,c1,c0,c1}  (bias as C; m16n8k16 f16 -> f32)
__device__ __forceinline__ void mma_f16_bias(float d[4],
                                             uint32_t a0, uint32_t a1, uint32_t a2, uint32_t a3,
                                             uint32_t b0, uint32_t b1, float c0, float c1) {
    asm("mma.sync.aligned.m16n8k16.row.col.f32.f16.f16.f32 "
        "{%0,%1,%2,%3}, {%4,%5,%6,%7}, {%8,%9}, {%10,%11,%10,%11};\n"
        : "=f"(d[0]), "=f"(d[1]), "=f"(d[2]), "=f"(d[3])
        : "r"(a0), "r"(a1), "r"(a2), "r"(a3), "r"(b0), "r"(b1), "f"(c0), "f"(c1));
}

// ============================================================================
// pre1: base, U1, U2 (f32) + zero-init d_out
// ============================================================================
__global__ void __launch_bounds__(256) pre1_kernel(const float* __restrict__ x,
                                                   const float* __restrict__ x1,
                                                   const float* __restrict__ x2,
                                                   const float* __restrict__ W1,
                                                   const float* __restrict__ b1,
                                                   float* __restrict__ out) {
    int t = blockIdx.x * 256 + threadIdx.x;
    if (t < 8192) out[t] = 0.f;
    if (t >= 16384) return;
    int o = t & 15;
    int row = t >> 4;
    if (row < 512) {
        const float* xr = x + row * 16;
        float s = b1[o];
        #pragma unroll
        for (int c = 0; c < 16; ++c)
            s += xr[c] * (W1[c * 16 + o] - W1[(16 + c) * 16 + o] - W1[(32 + c) * 16 + o]);
        g_base[row * 16 + o] = s;
    } else if (row < 768) {
        int r = row - 512;
        const float* xr = x1 + r * 16;
        float s = 0.f;
        #pragma unroll
        for (int c = 0; c < 16; ++c)
            s += xr[c] * W1[(16 + c) * 16 + o];
        g_U1[r * 16 + o] = s;
    } else {
        int r = row - 768;
        const float* xr = x2 + r * 16;
        float s = 0.f;
        #pragma unroll
        for (int c = 0; c < 16; ++c)
            s += xr[c] * W1[(32 + c) * 16 + o];
        g_U2[r * 16 + o] = s;
    }
}

// ============================================================================
// pre2: build f16 fragment-layout images
//   blocks 0..127 : w-image, thread = (bn, kt, g)
//   block  128    : u1-image, thread = (b, j)
// ============================================================================
__global__ void __launch_bounds__(256) pre2_kernel() {
    int tid = threadIdx.x;
    if (blockIdx.x < 128) {
        int idx = blockIdx.x * 256 + tid;     // 32768 = 512 bn x 8 kt x 8 g
        int bn = idx >> 6;
        int rem = idx & 63;
        int kt = rem >> 3;
        int g = rem & 7;
        int b = bn >> 8;
        int r1 = kt * 16 + g;
        const float* basep = g_base + bn * 16;
        const float* u2a = g_U2 + (b * 128 + r1) * 16;
        const float* u2b = u2a + 8 * 16;
        float w1[16], w2[16];
        #pragma unroll
        for (int o = 0; o < 16; ++o) {
            float bs = basep[o];
            w1[o] = bs + u2a[o];
            w2[o] = bs + u2b[o];
        }
        uint4* dst = g_wh + ((bn * 8 + kt) * 8 + g) * 4;
        #pragma unroll
        for (int t4 = 0; t4 < 4; ++t4) {
            uint4 e;
            e.x = pack_h2(w1[2 * t4],     w1[2 * t4 + 1]);      // row g,   cols lo
            e.y = pack_h2(w2[2 * t4],     w2[2 * t4 + 1]);      // row g+8, cols lo
            e.z = pack_h2(w1[2 * t4 + 8], w1[2 * t4 + 9]);      // row g,   cols hi
            e.w = pack_h2(w2[2 * t4 + 8], w2[2 * t4 + 9]);      // row g+8, cols hi
            dst[t4] = e;
        }
    } else {
        int b = tid >> 7;
        int j = tid & 127;
        const float* u1p = g_U1 + (b * 128 + j) * 16;
        uint2* dst = g_u1h + (b * 128 + j) * 4;
        #pragma unroll
        for (int t4 = 0; t4 < 4; ++t4) {
            uint2 e;
            e.x = pack_h2(u1p[2 * t4],     u1p[2 * t4 + 1]);
            e.y = pack_h2(u1p[2 * t4 + 8], u1p[2 * t4 + 9]);
            dst[t4] = e;
        }
    }
}

// ============================================================================
// main kernel
// ============================================================================
__global__ void __launch_bounds__(128, 6)
main_kernel(const float* __restrict__ W2, const float* __restrict__ b2,
            float* __restrict__ out) {
    __shared__ uint4 sW[8][8][4];    // [kt][g][t4]  4KB
    __shared__ uint2 sU[16][4];      // [j_local][t4] 512B
    __shared__ float sRed[4][16];

    const int tid = threadIdx.x;
    const int wid = tid >> 5;
    const int lane = tid & 31;
    const int g = lane >> 2;
    const int t4 = lane & 3;
    const int bn = blockIdx.x >> 3;
    const int s = blockIdx.x & 7;    // j octet
    const int b = bn >> 8;

    // ---- SMEM setup: straight copies of pre-permuted images ----
    {
        const uint4* src = g_wh + bn * 256;
        uint4* dstW = &sW[0][0][0];
        dstW[tid] = src[tid];
        dstW[tid + 128] = src[tid + 128];
    }
    if (tid < 64) {
        ((uint2*)sU)[tid] = g_u1h[(b * 128 + s * 16) * 4 + tid];
    }

    // ---- B fragments (W2 -> f16 RN) + bias ----
    uint32_t Bf[2][2];
    #pragma unroll
    for (int nt = 0; nt < 2; ++nt) {
        int n = nt * 8 + g;
        Bf[nt][0] = pack_h2(W2[(2 * t4) * 16 + n],     W2[(2 * t4 + 1) * 16 + n]);
        Bf[nt][1] = pack_h2(W2[(2 * t4 + 8) * 16 + n], W2[(2 * t4 + 9) * 16 + n]);
    }
    const float bm0 = b2[2 * t4],     bm1 = b2[2 * t4 + 1];
    const float bs0 = b2[8 + 2 * t4], bs1 = b2[8 + 2 * t4 + 1];

    float accm0 = 0.f, accm1 = 0.f;
    float accs0 = 0.f, accs1 = 0.f;
    const __half2 hz = __floats2half2_rn(0.f, 0.f);

    __syncthreads();

    // ---- main loop: 4 j x 8 k-tiles per warp ----
    #pragma unroll 1
    for (int jj = 0; jj < 4; ++jj) {
        const uint2 uu = sU[wid * 4 + jj][t4];
        const __half2 u_lo = *reinterpret_cast<const __half2*>(&uu.x);
        const __half2 u_hi = *reinterpret_cast<const __half2*>(&uu.y);
        #pragma unroll
        for (int kt = 0; kt < 8; ++kt) {
            const uint4 q = sW[kt][g][t4];
            // A = relu(w + u1) in f16x2 (fragment layout)
            uint32_t a0 = h2u(__hmax2(__hadd2(*reinterpret_cast<const __half2*>(&q.x), u_lo), hz));
            uint32_t a1 = h2u(__hmax2(__hadd2(*reinterpret_cast<const __half2*>(&q.y), u_lo), hz));
            uint32_t a2 = h2u(__hmax2(__hadd2(*reinterpret_cast<const __half2*>(&q.z), u_hi), hz));
            uint32_t a3 = h2u(__hmax2(__hadd2(*reinterpret_cast<const __half2*>(&q.w), u_hi), hz));

            float dm[4], ds[4];
            mma_f16_bias(dm, a0, a1, a2, a3, Bf[0][0], Bf[0][1], bm0, bm1);
            mma_f16_bias(ds, a0, a1, a2, a3, Bf[1][0], Bf[1][1], bs0, bs1);

            // max half (relu folded: acc >= 0)
            accm0 = fmaxf(accm0, fmaxf(dm[0], dm[2]));
            accm1 = fmaxf(accm1, fmaxf(dm[1], dm[3]));
            // mean half
            accs0 += fmaxf(ds[0], 0.f) + fmaxf(ds[2], 0.f);
            accs1 += fmaxf(ds[1], 0.f) + fmaxf(ds[3], 0.f);
        }
    }

    // ---- intra-warp reduction over g lanes ----
    #pragma unroll
    for (int sh = 4; sh <= 16; sh <<= 1) {
        accm0 = fmaxf(accm0, __shfl_xor_sync(0xffffffffu, accm0, sh));
        accm1 = fmaxf(accm1, __shfl_xor_sync(0xffffffffu, accm1, sh));
        accs0 += __shfl_xor_sync(0xffffffffu, accs0, sh);
        accs1 += __shfl_xor_sync(0xffffffffu, accs1, sh);
    }
    if (lane < 4) {
        sRed[wid][2 * lane]         = accm0;
        sRed[wid][2 * lane + 1]     = accm1;
        sRed[wid][8 + 2 * lane]     = accs0;
        sRed[wid][8 + 2 * lane + 1] = accs1;
    }
    __syncthreads();

    // ---- cross-warp combine + atomic merge ----
    if (tid < 16) {
        float v = sRed[0][tid];
        if (tid < 8) {
            #pragma unroll
            for (int w = 1; w < 4; ++w) v = fmaxf(v, sRed[w][tid]);
            atomicMax((int*)(out + bn * 16 + tid), __float_as_int(v));  // v >= 0
        } else {
            #pragma unroll
            for (int w = 1; w < 4; ++w) v += sRed[w][tid];
            atomicAdd(out + bn * 16 + tid, v * (1.0f / 16384.0f));
        }
    }
}

// ============================================================================
// Launch
// ============================================================================
extern "C" void kernel_launch(void* const* d_in, const int* in_sizes, int n_in,
                              void* d_out, int out_size) {
    const float* x  = (const float*)d_in[0];
    const float* x1 = (const float*)d_in[1];
    const float* x2 = (const float*)d_in[2];
    const float* W1 = (const float*)d_in[3];
    const float* b1 = (const float*)d_in[4];
    const float* W2 = (const float*)d_in[5];
    const float* b2 = (const float*)d_in[6];
    float* out = (float*)d_out;

    pre1_kernel<<<64, 256>>>(x, x1, x2, W1, b1, out);
    pre2_kernel<<<129, 256>>>();
    main_kernel<<<4096, 128>>>(W2, b2, out);
}

// round 7
// speedup vs baseline: 1.8990x; 1.0439x over previous
#include <cuda_runtime.h>
#include <cuda_fp16.h>
#include <cstdint>

// ============================================================================
// PointPairwiseRelation3 — fp16 mma.sync m16n8k16, fused pre-pass
//
//   pre[b,n,j,k,o] = base[b,n,o] + U1[b,j,o] + U2[b,k,o]
//     base = x@(Wa-Wb-Wc) + b1,  U1 = x1@Wb,  U2 = x2@Wc
//   h = relu(pre);  u = relu(h @ W2 + b2)
//   out[b,n,p] = max_{j,k} u   (p<8) ;  mean_{j,k} u  (p>=8)
//
// pre_kernel (fused, 129 blocks):
//   blocks 0..127: recompute U2[b] + base rows in SMEM, emit w-image
//                  g_wh[bn][kt][g][t4] (f16x2 fragment layout)
//   block 128:     U1 -> u1-image g_u1h[b][j][t4]; zero d_out
// main_kernel: 4096 CTAs = (b,n) x 8 j-octets, 128 thr, 8 CTAs/SM.
//   Warp: 4 j x 8 k-tiles; per tile 1 LDS.128 + 4 HADD2 + 4 HMAX2 + 2 HMMA
//   + 12 epi. Partials merged with atomicMax(bits)/atomicAdd.
// ============================================================================

__device__ uint4 g_wh[512 * 8 * 8 * 4];   // [bn][kt][g][t4] -> 2MB
__device__ uint2 g_u1h[2 * 128 * 4];      // [b][j][t4]

__device__ __forceinline__ uint32_t h2u(__half2 h) {
    return *reinterpret_cast<uint32_t*>(&h);
}
__device__ __forceinline__ uint32_t pack_h2(float lo, float hi) {
    __half2 h = __floats2half2_rn(lo, hi);
    return h2u(h);
}

// D = A*B + {c0,c1,c0,c1}  (bias as C; m16n8k16 f16 -> f32)
__device__ __forceinline__ void mma_f16_bias(float d[4],
                                             uint32_t a0, uint32_t a1, uint32_t a2, uint32_t a3,
                                             uint32_t b0, uint32_t b1, float c0, float c1) {
    asm("mma.sync.aligned.m16n8k16.row.col.f32.f16.f16.f32 "
        "{%0,%1,%2,%3}, {%4,%5,%6,%7}, {%8,%9}, {%10,%11,%10,%11};\n"
        : "=f"(d[0]), "=f"(d[1]), "=f"(d[2]), "=f"(d[3])
        : "r"(a0), "r"(a1), "r"(a2), "r"(a3), "r"(b0), "r"(b1), "f"(c0), "f"(c1));
}

// ============================================================================
// Fused pre kernel
// ============================================================================
__global__ void __launch_bounds__(256) pre_kernel(const float* __restrict__ x,
                                                  const float* __restrict__ x1,
                                                  const float* __restrict__ x2,
                                                  const float* __restrict__ W1,
                                                  const float* __restrict__ b1,
                                                  float* __restrict__ out) {
    const int t = threadIdx.x;
    if (blockIdx.x < 128) {
        // ---- w-image for bn in [blk*4, blk*4+4) ----
        __shared__ float sU2[128][16];
        __shared__ float sBase[4][16];
        const int b = blockIdx.x >> 6;            // 0..63 -> b=0, 64..127 -> b=1
        const int bn0 = blockIdx.x * 4;

        // U2[b] : 2048 outputs, 8 per thread (K=16 dots)
        #pragma unroll
        for (int kk = 0; kk < 8; ++kk) {
            int idx = t + kk * 256;
            int r = idx >> 4, o = idx & 15;
            const float* xr = x2 + (b * 128 + r) * 16;
            float s = 0.f;
            #pragma unroll
            for (int c = 0; c < 16; ++c)
                s += xr[c] * W1[(32 + c) * 16 + o];
            sU2[r][o] = s;
        }
        // base rows for 4 bn
        if (t < 64) {
            int bnl = t >> 4, o = t & 15;
            const float* xr = x + (bn0 + bnl) * 16;
            float s = b1[o];
            #pragma unroll
            for (int c = 0; c < 16; ++c)
                s += xr[c] * (W1[c * 16 + o] - W1[(16 + c) * 16 + o] - W1[(32 + c) * 16 + o]);
            sBase[bnl][o] = s;
        }
        __syncthreads();

        // pack: thread = (bn_local, kt, g)
        const int bnl = t >> 6;
        const int rem = t & 63;
        const int kt = rem >> 3;
        const int g = rem & 7;
        const int r1 = kt * 16 + g;
        float w1[16], w2[16];
        #pragma unroll
        for (int o = 0; o < 16; ++o) {
            float bs = sBase[bnl][o];
            w1[o] = bs + sU2[r1][o];
            w2[o] = bs + sU2[r1 + 8][o];
        }
        uint4* dst = g_wh + (((bn0 + bnl) * 8 + kt) * 8 + g) * 4;
        #pragma unroll
        for (int t4 = 0; t4 < 4; ++t4) {
            uint4 e;
            e.x = pack_h2(w1[2 * t4],     w1[2 * t4 + 1]);   // row g,   cols lo
            e.y = pack_h2(w2[2 * t4],     w2[2 * t4 + 1]);   // row g+8, cols lo
            e.z = pack_h2(w1[2 * t4 + 8], w1[2 * t4 + 9]);   // row g,   cols hi
            e.w = pack_h2(w2[2 * t4 + 8], w2[2 * t4 + 9]);   // row g+8, cols hi
            dst[t4] = e;
        }
    } else {
        // ---- u1-image + zero d_out ----
        const int b = t >> 7;
        const int j = t & 127;
        const float* xr = x1 + (b * 128 + j) * 16;
        float u[16];
        #pragma unroll
        for (int o = 0; o < 16; ++o) {
            float s = 0.f;
            #pragma unroll
            for (int c = 0; c < 16; ++c)
                s += xr[c] * W1[(16 + c) * 16 + o];
            u[o] = s;
        }
        uint2* dst = g_u1h + (b * 128 + j) * 4;
        #pragma unroll
        for (int t4 = 0; t4 < 4; ++t4) {
            uint2 e;
            e.x = pack_h2(u[2 * t4],     u[2 * t4 + 1]);
            e.y = pack_h2(u[2 * t4 + 8], u[2 * t4 + 9]);
            dst[t4] = e;
        }
        #pragma unroll
        for (int i = 0; i < 32; ++i)
            out[t + i * 256] = 0.f;
    }
}

// ============================================================================
// main kernel
// ============================================================================
__global__ void __launch_bounds__(128, 8)
main_kernel(const float* __restrict__ W2, const float* __restrict__ b2,
            float* __restrict__ out) {
    __shared__ uint4 sW[8][8][4];    // [kt][g][t4]  4KB
    __shared__ uint2 sU[16][4];      // [j_local][t4] 512B
    __shared__ float sRed[4][16];

    const int tid = threadIdx.x;
    const int wid = tid >> 5;
    const int lane = tid & 31;
    const int g = lane >> 2;
    const int t4 = lane & 3;
    const int bn = blockIdx.x >> 3;
    const int s = blockIdx.x & 7;    // j octet
    const int b = bn >> 8;

    // ---- SMEM setup: straight copies of pre-permuted images ----
    {
        const uint4* src = g_wh + bn * 256;
        uint4* dstW = &sW[0][0][0];
        dstW[tid] = src[tid];
        dstW[tid + 128] = src[tid + 128];
    }
    if (tid < 64) {
        ((uint2*)sU)[tid] = g_u1h[(b * 128 + s * 16) * 4 + tid];
    }

    // ---- B fragments (W2 -> f16 RN) + bias ----
    uint32_t Bf[2][2];
    #pragma unroll
    for (int nt = 0; nt < 2; ++nt) {
        int n = nt * 8 + g;
        Bf[nt][0] = pack_h2(W2[(2 * t4) * 16 + n],     W2[(2 * t4 + 1) * 16 + n]);
        Bf[nt][1] = pack_h2(W2[(2 * t4 + 8) * 16 + n], W2[(2 * t4 + 9) * 16 + n]);
    }
    const float bm0 = b2[2 * t4],     bm1 = b2[2 * t4 + 1];
    const float bs0 = b2[8 + 2 * t4], bs1 = b2[8 + 2 * t4 + 1];

    float accm0 = 0.f, accm1 = 0.f;
    float accs0 = 0.f, accs1 = 0.f;
    const __half2 hz = __floats2half2_rn(0.f, 0.f);

    __syncthreads();

    // ---- main loop: 4 j x 8 k-tiles per warp ----
    #pragma unroll 1
    for (int jj = 0; jj < 4; ++jj) {
        const uint2 uu = sU[wid * 4 + jj][t4];
        const __half2 u_lo = *reinterpret_cast<const __half2*>(&uu.x);
        const __half2 u_hi = *reinterpret_cast<const __half2*>(&uu.y);
        #pragma unroll
        for (int kt = 0; kt < 8; ++kt) {
            const uint4 q = sW[kt][g][t4];
            // A = relu(w + u1) in f16x2 (fragment layout)
            uint32_t a0 = h2u(__hmax2(__hadd2(*reinterpret_cast<const __half2*>(&q.x), u_lo), hz));
            uint32_t a1 = h2u(__hmax2(__hadd2(*reinterpret_cast<const __half2*>(&q.y), u_lo), hz));
            uint32_t a2 = h2u(__hmax2(__hadd2(*reinterpret_cast<const __half2*>(&q.z), u_hi), hz));
            uint32_t a3 = h2u(__hmax2(__hadd2(*reinterpret_cast<const __half2*>(&q.w), u_hi), hz));

            float dm[4], ds[4];
            mma_f16_bias(dm, a0, a1, a2, a3, Bf[0][0], Bf[0][1], bm0, bm1);
            mma_f16_bias(ds, a0, a1, a2, a3, Bf[1][0], Bf[1][1], bs0, bs1);

            // max half (relu folded: acc >= 0)
            accm0 = fmaxf(accm0, fmaxf(dm[0], dm[2]));
            accm1 = fmaxf(accm1, fmaxf(dm[1], dm[3]));
            // mean half
            accs0 += fmaxf(ds[0], 0.f) + fmaxf(ds[2], 0.f);
            accs1 += fmaxf(ds[1], 0.f) + fmaxf(ds[3], 0.f);
        }
    }

    // ---- intra-warp reduction over g lanes ----
    #pragma unroll
    for (int sh = 4; sh <= 16; sh <<= 1) {
        accm0 = fmaxf(accm0, __shfl_xor_sync(0xffffffffu, accm0, sh));
        accm1 = fmaxf(accm1, __shfl_xor_sync(0xffffffffu, accm1, sh));
        accs0 += __shfl_xor_sync(0xffffffffu, accs0, sh);
        accs1 += __shfl_xor_sync(0xffffffffu, accs1, sh);
    }
    if (lane < 4) {
        sRed[wid][2 * lane]         = accm0;
        sRed[wid][2 * lane + 1]     = accm1;
        sRed[wid][8 + 2 * lane]     = accs0;
        sRed[wid][8 + 2 * lane + 1] = accs1;
    }
    __syncthreads();

    // ---- cross-warp combine + atomic merge ----
    if (tid < 16) {
        float v = sRed[0][tid];
        if (tid < 8) {
            #pragma unroll
            for (int w = 1; w < 4; ++w) v = fmaxf(v, sRed[w][tid]);
            atomicMax((int*)(out + bn * 16 + tid), __float_as_int(v));  // v >= 0
        } else {
            #pragma unroll
            for (int w = 1; w < 4; ++w) v += sRed[w][tid];
            atomicAdd(out + bn * 16 + tid, v * (1.0f / 16384.0f));
        }
    }
}

// ============================================================================
// Launch
// ============================================================================
extern "C" void kernel_launch(void* const* d_in, const int* in_sizes, int n_in,
                              void* d_out, int out_size) {
    const float* x  = (const float*)d_in[0];
    const float* x1 = (const float*)d_in[1];
    const float* x2 = (const float*)d_in[2];
    const float* W1 = (const float*)d_in[3];
    const float* b1 = (const float*)d_in[4];
    const float* W2 = (const float*)d_in[5];
    const float* b2 = (const float*)d_in[6];
    float* out = (float*)d_out;

    pre_kernel<<<129, 256>>>(x, x1, x2, W1, b1, out);
    main_kernel<<<4096, 128>>>(W2, b2, out);
}